// round 7
// baseline (speedup 1.0000x reference)
#include <cuda_runtime.h>
#include <cuda_bf16.h>
#include <cstdint>
#include <math.h>

// Problem dims
#define BROWS 65536
#define KDIM  512
#define VDIM  512
#define NSPLIT 16
#define ROWS_PER_SPLIT (BROWS / NSPLIT)   // 4096

// -------- device scratch (static; no cudaMalloc allowed) --------------------
__device__ float g_colsum[KDIM];
__device__ float g_loss;
__device__ float g_gates[3];
__device__ float g_partials[NSPLIT][VDIM * KDIM];                 // 16 MB
__device__ __nv_bfloat16 g_khi[(size_t)BROWS * KDIM];             // 64 MB
__device__ __nv_bfloat16 g_klo[(size_t)BROWS * KDIM];             // 64 MB
__device__ __nv_bfloat16 g_diff[(size_t)BROWS * VDIM];            // 64 MB
__device__ __nv_bfloat16 g_Whi[VDIM * KDIM];
__device__ __nv_bfloat16 g_Wlo[VDIM * KDIM];

// ===================== PTX helpers (baseline sm_80+/sm_90 ISA only) =========
__device__ __forceinline__ uint32_t smem_u32(const void* p) {
    uint32_t a;
    asm("{ .reg .u64 t; cvta.to.shared.u64 t, %1; cvt.u32.u64 %0, t; }"
        : "=r"(a) : "l"(p));
    return a;
}
__device__ __forceinline__ void ldmx4(uint32_t addr, uint32_t r[4]) {
    asm volatile("ldmatrix.sync.aligned.m8n8.x4.shared.b16 {%0,%1,%2,%3}, [%4];"
                 : "=r"(r[0]), "=r"(r[1]), "=r"(r[2]), "=r"(r[3]) : "r"(addr));
}
__device__ __forceinline__ void ldmx4t(uint32_t addr, uint32_t r[4]) {
    asm volatile("ldmatrix.sync.aligned.m8n8.x4.trans.shared.b16 {%0,%1,%2,%3}, [%4];"
                 : "=r"(r[0]), "=r"(r[1]), "=r"(r[2]), "=r"(r[3]) : "r"(addr));
}
__device__ __forceinline__ void mma16816(float c[4], const uint32_t a[4],
                                         uint32_t b0, uint32_t b1) {
    asm volatile(
        "mma.sync.aligned.m16n8k16.row.col.f32.bf16.bf16.f32 "
        "{%0,%1,%2,%3}, {%4,%5,%6,%7}, {%8,%9}, {%0,%1,%2,%3};"
        : "+f"(c[0]), "+f"(c[1]), "+f"(c[2]), "+f"(c[3])
        : "r"(a[0]), "r"(a[1]), "r"(a[2]), "r"(a[3]), "r"(b0), "r"(b1));
}
__device__ __forceinline__ void cpasync16(uint32_t dst, const void* src) {
    asm volatile("cp.async.cg.shared.global [%0], [%1], 16;"
                 :: "r"(dst), "l"(src));
}
#define CP_COMMIT() asm volatile("cp.async.commit_group;" ::: "memory")
#define CP_WAIT(n)  asm volatile("cp.async.wait_group %0;" :: "n"(n) : "memory")

// ---------------------------------------------------------------------------
__global__ void zero_kernel() {
    int t = threadIdx.x;
    if (t < KDIM) g_colsum[t] = 0.0f;
    if (t == 0) g_loss = 0.0f;
}

// ---------------------------------------------------------------------------
// Fused: split fp32 k -> bf16 hi/lo  AND column sums (gate input).
// Block handles 128 rows x 512 cols. 512 blocks.
__global__ __launch_bounds__(256)
void convert_k_colsum(const float* __restrict__ src) {
    __shared__ float s[2][KDIM];
    const int tid = threadIdx.x;
    const int h = tid >> 7;               // row half 0/1
    const int c4 = (tid & 127) * 4;       // 4-col chunk
    const size_t r0 = (size_t)blockIdx.x * 128 + h * 64;

    float4 sum = make_float4(0.f, 0.f, 0.f, 0.f);
    for (int r = 0; r < 64; r++) {
        size_t idx = (r0 + r) * KDIM + c4;
        float4 x = *(const float4*)(src + idx);
        sum.x += x.x; sum.y += x.y; sum.z += x.z; sum.w += x.w;
        __nv_bfloat16 h0 = __float2bfloat16_rn(x.x);
        __nv_bfloat16 h1 = __float2bfloat16_rn(x.y);
        __nv_bfloat16 h2 = __float2bfloat16_rn(x.z);
        __nv_bfloat16 h3 = __float2bfloat16_rn(x.w);
        __nv_bfloat16 l0 = __float2bfloat16_rn(x.x - __bfloat162float(h0));
        __nv_bfloat16 l1 = __float2bfloat16_rn(x.y - __bfloat162float(h1));
        __nv_bfloat16 l2 = __float2bfloat16_rn(x.z - __bfloat162float(h2));
        __nv_bfloat16 l3 = __float2bfloat16_rn(x.w - __bfloat162float(h3));
        uint2 uh, ul;
        uh.x = ((uint32_t)__bfloat16_as_ushort(h1) << 16) | __bfloat16_as_ushort(h0);
        uh.y = ((uint32_t)__bfloat16_as_ushort(h3) << 16) | __bfloat16_as_ushort(h2);
        ul.x = ((uint32_t)__bfloat16_as_ushort(l1) << 16) | __bfloat16_as_ushort(l0);
        ul.y = ((uint32_t)__bfloat16_as_ushort(l3) << 16) | __bfloat16_as_ushort(l2);
        *(uint2*)(g_khi + idx) = uh;
        *(uint2*)(g_klo + idx) = ul;
    }
    *(float4*)&s[h][c4] = sum;
    __syncthreads();
    float a = s[0][tid] + s[1][tid];
    atomicAdd(&g_colsum[tid], a);
    float b = s[0][tid + 256] + s[1][tid + 256];
    atomicAdd(&g_colsum[tid + 256], b);
}

// ---------------------------------------------------------------------------
// Split fp32 -> bf16 hi/lo pair (for W only).
__global__ void convert_split_kernel(const float* __restrict__ src,
                                     __nv_bfloat16* __restrict__ dhi,
                                     __nv_bfloat16* __restrict__ dlo) {
    size_t i = ((size_t)blockIdx.x * 256 + threadIdx.x) * 4;
    float4 x = *(const float4*)(src + i);
    __nv_bfloat16 h0 = __float2bfloat16_rn(x.x);
    __nv_bfloat16 h1 = __float2bfloat16_rn(x.y);
    __nv_bfloat16 h2 = __float2bfloat16_rn(x.z);
    __nv_bfloat16 h3 = __float2bfloat16_rn(x.w);
    __nv_bfloat16 l0 = __float2bfloat16_rn(x.x - __bfloat162float(h0));
    __nv_bfloat16 l1 = __float2bfloat16_rn(x.y - __bfloat162float(h1));
    __nv_bfloat16 l2 = __float2bfloat16_rn(x.z - __bfloat162float(h2));
    __nv_bfloat16 l3 = __float2bfloat16_rn(x.w - __bfloat162float(h3));
    uint2 uh, ul;
    uh.x = ((uint32_t)__bfloat16_as_ushort(h1) << 16) | __bfloat16_as_ushort(h0);
    uh.y = ((uint32_t)__bfloat16_as_ushort(h3) << 16) | __bfloat16_as_ushort(h2);
    ul.x = ((uint32_t)__bfloat16_as_ushort(l1) << 16) | __bfloat16_as_ushort(l0);
    ul.y = ((uint32_t)__bfloat16_as_ushort(l3) << 16) | __bfloat16_as_ushort(l2);
    *(uint2*)(dhi + i) = uh;
    *(uint2*)(dlo + i) = ul;
}

// ---------------------------------------------------------------------------
// GEMM1 via HMMA: retrieved = k @ W.T, bf16 split-2, 3-pass.
// CTA 128x128, BK=32, 8 warps (2x4), warp tile 64x32.
// 3-stage cp.async pipeline (prefetch distance 2), ONE barrier per chunk.
// Smem: XOR-swizzled 64B-pitch rows (no padding), 32KB/stage, 3 stages.
#define G1_TILE   8192                   // 128 rows x 64 B
#define G1_STAGE  (4 * G1_TILE)          // Ahi Alo Bhi Blo = 32768 B
#define G1_SMEM   (3 * G1_STAGE)         // 98304 B
#define G1_NCHUNK 16

// swizzled byte offset of 16B chunk `c` (0..3) in row `row` (64B pitch)
__device__ __forceinline__ uint32_t sw1(int row, int c) {
    return (uint32_t)(row * 64 + ((c ^ ((row >> 1) & 3)) << 4));
}

__device__ __forceinline__ void g1_prefetch(uint32_t sb, int kc,
                                            size_t gA, size_t gB,
                                            int lrow, int lc) {
    const uint32_t st = sb + (uint32_t)(kc % 3) * G1_STAGE;
    const size_t col = (size_t)kc * 32;
#pragma unroll
    for (int u = 0; u < 2; u++) {
        const int c = lc + u;
        const uint32_t o = sw1(lrow, c);
        const size_t ga = gA + col + c * 8;
        const size_t gb = gB + col + c * 8;
        cpasync16(st + o,               g_khi + ga);
        cpasync16(st + G1_TILE + o,     g_klo + ga);
        cpasync16(st + 2 * G1_TILE + o, g_Whi + gb);
        cpasync16(st + 3 * G1_TILE + o, g_Wlo + gb);
    }
    CP_COMMIT();
}

__global__ __launch_bounds__(256, 2)
void gemm1_hmma(const float* __restrict__ v, float* __restrict__ out) {
    extern __shared__ char smem[];
    const uint32_t sbase = smem_u32(smem);
    const int tid = threadIdx.x;
    const int lane = tid & 31;
    const int wid = tid >> 5;
    const int n0 = blockIdx.x * 128;
    const int m0 = blockIdx.y * 128;

    // global->smem mapping: thread -> (row, 2 chunks of 16B)
    const int lrow = tid >> 1;
    const int lc = (tid & 1) * 2;
    const size_t gA = (size_t)(m0 + lrow) * KDIM;
    const size_t gB = (size_t)(n0 + lrow) * KDIM;

    float acc[4][4][4];
#pragma unroll
    for (int a = 0; a < 4; a++)
#pragma unroll
        for (int b = 0; b < 4; b++)
#pragma unroll
            for (int c = 0; c < 4; c++) acc[a][b][c] = 0.0f;

    g1_prefetch(sbase, 0, gA, gB, lrow, lc);
    g1_prefetch(sbase, 1, gA, gB, lrow, lc);

    const int wm = wid >> 2;      // 0..1
    const int wn = wid & 3;       // 0..3
    const int ri = lane & 7;
    const int q = lane >> 3;
    const int rowoff = (q & 1) * 8 + ri;   // row within 16-row tile
    const int cq = q >> 1;                 // k 16B-chunk select within k16

#pragma unroll 1
    for (int kc = 0; kc < G1_NCHUNK; kc++) {
        if (kc + 1 < G1_NCHUNK) { CP_WAIT(1); } else { CP_WAIT(0); }
        __syncthreads();
        if (kc + 2 < G1_NCHUNK) g1_prefetch(sbase, kc + 2, gA, gB, lrow, lc);

        const uint32_t bA = sbase + (uint32_t)(kc % 3) * G1_STAGE;
#pragma unroll
        for (int ks = 0; ks < 2; ks++) {
            const int c = ks * 2 + cq;
            uint32_t bh[2][4], bl[2][4];
#pragma unroll
            for (int nt = 0; nt < 2; nt++) {
                const int rB = wn * 32 + nt * 16 + rowoff;
                uint32_t addr = bA + 2 * G1_TILE + sw1(rB, c);
                ldmx4(addr, bh[nt]);
                ldmx4(addr + G1_TILE, bl[nt]);
            }
#pragma unroll
            for (int mi = 0; mi < 4; mi++) {
                const int rA = wm * 64 + mi * 16 + rowoff;
                uint32_t ah[4], al[4];
                uint32_t addr = bA + sw1(rA, c);
                ldmx4(addr, ah);
                ldmx4(addr + G1_TILE, al);
#pragma unroll
                for (int nj = 0; nj < 4; nj++) {
                    uint32_t b0h = bh[nj >> 1][nj & 1];
                    uint32_t b1h = bh[nj >> 1][2 + (nj & 1)];
                    uint32_t b0l = bl[nj >> 1][nj & 1];
                    uint32_t b1l = bl[nj >> 1][2 + (nj & 1)];
                    mma16816(acc[mi][nj], ah, b0h, b1h);   // hi*hi
                    mma16816(acc[mi][nj], al, b0h, b1h);   // lo*hi
                    mma16816(acc[mi][nj], ah, b0l, b1l);   // hi*lo
                }
            }
        }
    }

    // ---- epilogue: retrieved fp32, diff bf16, fused loss ----
    const int g = lane >> 2;
    const int t = lane & 3;
    float lp = 0.0f;
#pragma unroll
    for (int mi = 0; mi < 4; mi++) {
#pragma unroll
        for (int nj = 0; nj < 4; nj++) {
            int col = n0 + wn * 32 + nj * 8 + t * 2;
#pragma unroll
            for (int h = 0; h < 2; h++) {
                int row = m0 + wm * 64 + mi * 16 + g + h * 8;
                size_t off = (size_t)row * VDIM + col;
                float r0 = acc[mi][nj][2 * h];
                float r1 = acc[mi][nj][2 * h + 1];
                *(float2*)(out + off) = make_float2(r0, r1);
                float2 vv = *(const float2*)(v + off);
                float d0 = r0 - vv.x, d1 = r1 - vv.y;
                lp += d0 * d0 + d1 * d1;
                uint32_t db = ((uint32_t)__bfloat16_as_ushort(__float2bfloat16_rn(d1)) << 16)
                            | __bfloat16_as_ushort(__float2bfloat16_rn(d0));
                *(uint32_t*)(g_diff + off) = db;
            }
        }
    }

    __shared__ float red[256];
    red[tid] = lp;
    __syncthreads();
#pragma unroll
    for (int s = 128; s > 0; s >>= 1) {
        if (tid < s) red[tid] += red[tid + s];
        __syncthreads();
    }
    if (tid == 0) atomicAdd(&g_loss, red[0]);
}

// ---------------------------------------------------------------------------
// GEMM2 via HMMA: partial[s] = diff_split.T @ k_split (single-pass bf16).
// CTA 128(vd) x 128(kd), BK=64 batch rows, split-K over 16 splits.
// 3-stage pipeline, one barrier per chunk, XOR-swizzled 256B-pitch rows.
#define G2_TILE   16384                  // 64 rows x 256 B
#define G2_STAGE  (2 * G2_TILE)          // diff + k = 32768 B
#define G2_SMEM   (3 * G2_STAGE)         // 98304 B
#define G2_NCHUNK (ROWS_PER_SPLIT / 64)  // 64

// swizzled byte offset of 16B chunk `c` (0..15) in row `row` (256B pitch)
__device__ __forceinline__ uint32_t sw2(int row, int c) {
    return (uint32_t)(row * 256 + ((c ^ (row & 7)) << 4));
}

__device__ __forceinline__ void g2_prefetch(uint32_t sb, int bt, size_t b0,
                                            int vd0, int kd0, int lrow, int lc0) {
    const uint32_t st = sb + (uint32_t)(bt % 3) * G2_STAGE;
    const size_t gr = b0 + (size_t)bt * 64 + lrow;
#pragma unroll
    for (int u = 0; u < 4; u++) {
        const int c = lc0 + u;
        const uint32_t o = sw2(lrow, c);
        cpasync16(st + o,           g_diff + gr * VDIM + vd0 + c * 8);
        cpasync16(st + G2_TILE + o, g_khi + gr * KDIM + kd0 + c * 8);
    }
    CP_COMMIT();
}

__global__ __launch_bounds__(256, 2)
void gemm2_hmma() {
    extern __shared__ char smem[];
    const uint32_t sbase = smem_u32(smem);
    const int tid = threadIdx.x;
    const int lane = tid & 31;
    const int wid = tid >> 5;
    const int kd0 = blockIdx.x * 128;
    const int vd0 = blockIdx.y * 128;
    const int split = blockIdx.z;
    const size_t b0 = (size_t)split * ROWS_PER_SPLIT;

    // load mapping: thread -> (row of 64, 4 chunks of 16B)
    const int lrow = tid >> 2;
    const int lc0 = (tid & 3) * 4;

    float acc[4][4][4];
#pragma unroll
    for (int a = 0; a < 4; a++)
#pragma unroll
        for (int b = 0; b < 4; b++)
#pragma unroll
            for (int c = 0; c < 4; c++) acc[a][b][c] = 0.0f;

    g2_prefetch(sbase, 0, b0, vd0, kd0, lrow, lc0);
    g2_prefetch(sbase, 1, b0, vd0, kd0, lrow, lc0);

    const int wm = wid >> 2;
    const int wn = wid & 3;
    const int ri = lane & 7;
    const int q = lane >> 3;
    const int krowoff = (q >> 1) * 8 + ri;   // b-row within k16 block
    const int coloff = (q & 1) * 8;          // m/n column offset

#pragma unroll 1
    for (int bt = 0; bt < G2_NCHUNK; bt++) {
        if (bt + 1 < G2_NCHUNK) { CP_WAIT(1); } else { CP_WAIT(0); }
        __syncthreads();
        if (bt + 2 < G2_NCHUNK) g2_prefetch(sbase, bt + 2, b0, vd0, kd0, lrow, lc0);

        const uint32_t bA = sbase + (uint32_t)(bt % 3) * G2_STAGE;
#pragma unroll
        for (int ks = 0; ks < 4; ks++) {
            const int krow = ks * 16 + krowoff;
            uint32_t bf[2][4];
#pragma unroll
            for (int nt = 0; nt < 2; nt++) {
                const int col = wn * 32 + nt * 16 + coloff;
                ldmx4t(bA + G2_TILE + sw2(krow, col >> 3), bf[nt]);
            }
#pragma unroll
            for (int mi = 0; mi < 4; mi++) {
                const int col = wm * 64 + mi * 16 + coloff;
                uint32_t af[4];
                ldmx4t(bA + sw2(krow, col >> 3), af);
#pragma unroll
                for (int nj = 0; nj < 4; nj++) {
                    mma16816(acc[mi][nj], af,
                             bf[nj >> 1][nj & 1], bf[nj >> 1][2 + (nj & 1)]);
                }
            }
        }
    }

    // write split partials
    float* pb = g_partials[split];
    const int g = lane >> 2;
    const int t = lane & 3;
#pragma unroll
    for (int mi = 0; mi < 4; mi++) {
#pragma unroll
        for (int nj = 0; nj < 4; nj++) {
            int col = kd0 + wn * 32 + nj * 8 + t * 2;
#pragma unroll
            for (int h = 0; h < 2; h++) {
                int row = vd0 + wm * 64 + mi * 16 + g + h * 8;
                *(float2*)(pb + (size_t)row * KDIM + col) =
                    make_float2(acc[mi][nj][2 * h], acc[mi][nj][2 * h + 1]);
            }
        }
    }
}

// ---------------------------------------------------------------------------
__global__ void gates_kernel(const float* __restrict__ gate_w,
                             const float* __restrict__ gate_b) {
    int tid = threadIdx.x;
    int j = tid >> 5;
    int lane = tid & 31;
    float p = 0.0f;
    for (int i = lane; i < KDIM; i += 32) p += gate_w[j * KDIM + i] * g_colsum[i];
#pragma unroll
    for (int o = 16; o > 0; o >>= 1) p += __shfl_down_sync(0xffffffffu, p, o);
    if (lane == 0) {
        float x = p * (1.0f / (float)BROWS) + gate_b[j];
        g_gates[j] = 1.0f / (1.0f + expf(-x));
    }
}

// ---------------------------------------------------------------------------
__global__ void finalize_kernel(const float* __restrict__ W,
                                const float* __restrict__ S,
                                float* __restrict__ out) {
    int idx = blockIdx.x * blockDim.x + threadIdx.x;
    float alpha = g_gates[0];
    float eta = g_gates[1];
    float theta = g_gates[2];

    float g = 0.0f;
#pragma unroll
    for (int s = 0; s < NSPLIT; s++) g += g_partials[s][idx];
    g *= (2.0f / ((float)BROWS * (float)VDIM));

    float ns = eta * S[idx] - theta * g;
    float nw = (1.0f - alpha) * W[idx] + ns;

    const size_t RET = (size_t)BROWS * VDIM;
    out[RET + 1 + idx] = nw;
    out[RET + 1 + (size_t)VDIM * KDIM + idx] = ns;
    if (idx == 0) out[RET] = g_loss * (1.0f / ((float)BROWS * (float)VDIM));
}

// ---------------------------------------------------------------------------
extern "C" void kernel_launch(void* const* d_in, const int* in_sizes, int n_in,
                              void* d_out, int out_size) {
    const float* k  = (const float*)d_in[0];
    const float* v  = (const float*)d_in[1];
    const float* W  = (const float*)d_in[2];
    const float* S  = (const float*)d_in[3];
    const float* gw = (const float*)d_in[4];
    const float* gb = (const float*)d_in[5];
    float* out = (float*)d_out;

    cudaFuncSetAttribute(gemm1_hmma, cudaFuncAttributeMaxDynamicSharedMemorySize,
                         G1_SMEM);
    cudaFuncSetAttribute(gemm2_hmma, cudaFuncAttributeMaxDynamicSharedMemorySize,
                         G2_SMEM);

    __nv_bfloat16* whi; cudaGetSymbolAddress((void**)&whi, g_Whi);
    __nv_bfloat16* wlo; cudaGetSymbolAddress((void**)&wlo, g_Wlo);

    zero_kernel<<<1, 512>>>();
    convert_k_colsum<<<BROWS / 128, 256>>>(k);
    convert_split_kernel<<<(VDIM * KDIM) / 1024, 256>>>(W, whi, wlo);
    gemm1_hmma<<<dim3(4, BROWS / 128), 256, G1_SMEM>>>(v, out);
    gemm2_hmma<<<dim3(4, 4, NSPLIT), 256, G2_SMEM>>>();
    gates_kernel<<<1, 96>>>(gw, gb);
    finalize_kernel<<<(VDIM * KDIM) / 256, 256>>>(W, S, out);
}

// round 8
// speedup vs baseline: 1.0028x; 1.0028x over previous
#include <cuda_runtime.h>
#include <cuda_bf16.h>
#include <cstdint>
#include <math.h>

// Problem dims
#define BROWS 65536
#define KDIM  512
#define VDIM  512
#define NSPLIT 16
#define ROWS_PER_SPLIT (BROWS / NSPLIT)   // 4096

// -------- device scratch (static; no cudaMalloc allowed) --------------------
__device__ float g_colsum[KDIM];
__device__ float g_loss;
__device__ float g_gates[3];
__device__ float g_partials[NSPLIT][VDIM * KDIM];                 // 16 MB
__device__ __nv_bfloat16 g_khi[(size_t)BROWS * KDIM];             // 64 MB
__device__ __nv_bfloat16 g_klo[(size_t)BROWS * KDIM];             // 64 MB
__device__ __nv_bfloat16 g_diff[(size_t)BROWS * VDIM];            // 64 MB
__device__ __nv_bfloat16 g_Whi[VDIM * KDIM];
__device__ __nv_bfloat16 g_Wlo[VDIM * KDIM];

// ===================== PTX helpers (baseline sm_80+/sm_90 ISA only) =========
__device__ __forceinline__ uint32_t smem_u32(const void* p) {
    uint32_t a;
    asm("{ .reg .u64 t; cvta.to.shared.u64 t, %1; cvt.u32.u64 %0, t; }"
        : "=r"(a) : "l"(p));
    return a;
}
__device__ __forceinline__ void ldmx4(uint32_t addr, uint32_t r[4]) {
    asm volatile("ldmatrix.sync.aligned.m8n8.x4.shared.b16 {%0,%1,%2,%3}, [%4];"
                 : "=r"(r[0]), "=r"(r[1]), "=r"(r[2]), "=r"(r[3]) : "r"(addr));
}
__device__ __forceinline__ void ldmx4t(uint32_t addr, uint32_t r[4]) {
    asm volatile("ldmatrix.sync.aligned.m8n8.x4.trans.shared.b16 {%0,%1,%2,%3}, [%4];"
                 : "=r"(r[0]), "=r"(r[1]), "=r"(r[2]), "=r"(r[3]) : "r"(addr));
}
__device__ __forceinline__ void mma16816(float c[4], const uint32_t a[4],
                                         uint32_t b0, uint32_t b1) {
    asm volatile(
        "mma.sync.aligned.m16n8k16.row.col.f32.bf16.bf16.f32 "
        "{%0,%1,%2,%3}, {%4,%5,%6,%7}, {%8,%9}, {%0,%1,%2,%3};"
        : "+f"(c[0]), "+f"(c[1]), "+f"(c[2]), "+f"(c[3])
        : "r"(a[0]), "r"(a[1]), "r"(a[2]), "r"(a[3]), "r"(b0), "r"(b1));
}
__device__ __forceinline__ void cpasync16(uint32_t dst, const void* src) {
    asm volatile("cp.async.cg.shared.global [%0], [%1], 16;"
                 :: "r"(dst), "l"(src));
}
#define CP_COMMIT() asm volatile("cp.async.commit_group;" ::: "memory")
#define CP_WAIT(n)  asm volatile("cp.async.wait_group %0;" :: "n"(n) : "memory")

// ---------------------------------------------------------------------------
__global__ void zero_kernel() {
    int t = threadIdx.x;
    if (t < KDIM) g_colsum[t] = 0.0f;
    if (t == 0) g_loss = 0.0f;
}

// ---------------------------------------------------------------------------
// Fused: split fp32 k -> bf16 hi/lo  AND column sums (gate input).
// Block handles 128 rows x 512 cols. 512 blocks.
__global__ __launch_bounds__(256)
void convert_k_colsum(const float* __restrict__ src) {
    __shared__ float s[2][KDIM];
    const int tid = threadIdx.x;
    const int h = tid >> 7;               // row half 0/1
    const int c4 = (tid & 127) * 4;       // 4-col chunk
    const size_t r0 = (size_t)blockIdx.x * 128 + h * 64;

    float4 sum = make_float4(0.f, 0.f, 0.f, 0.f);
    for (int r = 0; r < 64; r++) {
        size_t idx = (r0 + r) * KDIM + c4;
        float4 x = *(const float4*)(src + idx);
        sum.x += x.x; sum.y += x.y; sum.z += x.z; sum.w += x.w;
        __nv_bfloat16 h0 = __float2bfloat16_rn(x.x);
        __nv_bfloat16 h1 = __float2bfloat16_rn(x.y);
        __nv_bfloat16 h2 = __float2bfloat16_rn(x.z);
        __nv_bfloat16 h3 = __float2bfloat16_rn(x.w);
        __nv_bfloat16 l0 = __float2bfloat16_rn(x.x - __bfloat162float(h0));
        __nv_bfloat16 l1 = __float2bfloat16_rn(x.y - __bfloat162float(h1));
        __nv_bfloat16 l2 = __float2bfloat16_rn(x.z - __bfloat162float(h2));
        __nv_bfloat16 l3 = __float2bfloat16_rn(x.w - __bfloat162float(h3));
        uint2 uh, ul;
        uh.x = ((uint32_t)__bfloat16_as_ushort(h1) << 16) | __bfloat16_as_ushort(h0);
        uh.y = ((uint32_t)__bfloat16_as_ushort(h3) << 16) | __bfloat16_as_ushort(h2);
        ul.x = ((uint32_t)__bfloat16_as_ushort(l1) << 16) | __bfloat16_as_ushort(l0);
        ul.y = ((uint32_t)__bfloat16_as_ushort(l3) << 16) | __bfloat16_as_ushort(l2);
        *(uint2*)(g_khi + idx) = uh;
        *(uint2*)(g_klo + idx) = ul;
    }
    *(float4*)&s[h][c4] = sum;
    __syncthreads();
    float a = s[0][tid] + s[1][tid];
    atomicAdd(&g_colsum[tid], a);
    float b = s[0][tid + 256] + s[1][tid + 256];
    atomicAdd(&g_colsum[tid + 256], b);
}

// ---------------------------------------------------------------------------
// Split fp32 -> bf16 hi/lo pair (for W only).
__global__ void convert_split_kernel(const float* __restrict__ src,
                                     __nv_bfloat16* __restrict__ dhi,
                                     __nv_bfloat16* __restrict__ dlo) {
    size_t i = ((size_t)blockIdx.x * 256 + threadIdx.x) * 4;
    float4 x = *(const float4*)(src + i);
    __nv_bfloat16 h0 = __float2bfloat16_rn(x.x);
    __nv_bfloat16 h1 = __float2bfloat16_rn(x.y);
    __nv_bfloat16 h2 = __float2bfloat16_rn(x.z);
    __nv_bfloat16 h3 = __float2bfloat16_rn(x.w);
    __nv_bfloat16 l0 = __float2bfloat16_rn(x.x - __bfloat162float(h0));
    __nv_bfloat16 l1 = __float2bfloat16_rn(x.y - __bfloat162float(h1));
    __nv_bfloat16 l2 = __float2bfloat16_rn(x.z - __bfloat162float(h2));
    __nv_bfloat16 l3 = __float2bfloat16_rn(x.w - __bfloat162float(h3));
    uint2 uh, ul;
    uh.x = ((uint32_t)__bfloat16_as_ushort(h1) << 16) | __bfloat16_as_ushort(h0);
    uh.y = ((uint32_t)__bfloat16_as_ushort(h3) << 16) | __bfloat16_as_ushort(h2);
    ul.x = ((uint32_t)__bfloat16_as_ushort(l1) << 16) | __bfloat16_as_ushort(l0);
    ul.y = ((uint32_t)__bfloat16_as_ushort(l3) << 16) | __bfloat16_as_ushort(l2);
    *(uint2*)(dhi + i) = uh;
    *(uint2*)(dlo + i) = ul;
}

// ---------------------------------------------------------------------------
// GEMM1 via HMMA: retrieved = k @ W.T, bf16 split-2, 3-pass.
// CTA 128x128, BK=32, 8 warps (2x4), warp tile 64x32.
// 3-stage cp.async pipeline (prefetch distance 2), ONE barrier per chunk.
// Smem: XOR-swizzled 64B-pitch rows (no padding), 32KB/stage, 3 stages.
#define G1_TILE   8192                   // 128 rows x 64 B
#define G1_STAGE  (4 * G1_TILE)          // Ahi Alo Bhi Blo = 32768 B
#define G1_SMEM   (3 * G1_STAGE)         // 98304 B
#define G1_NCHUNK 16

// swizzled byte offset of 16B chunk `c` (0..3) in row `row` (64B pitch)
__device__ __forceinline__ uint32_t sw1(int row, int c) {
    return (uint32_t)(row * 64 + ((c ^ ((row >> 1) & 3)) << 4));
}

__device__ __forceinline__ void g1_prefetch(uint32_t sb, int kc,
                                            size_t gA, size_t gB,
                                            int lrow, int lc) {
    const uint32_t st = sb + (uint32_t)(kc % 3) * G1_STAGE;
    const size_t col = (size_t)kc * 32;
#pragma unroll
    for (int u = 0; u < 2; u++) {
        const int c = lc + u;
        const uint32_t o = sw1(lrow, c);
        const size_t ga = gA + col + c * 8;
        const size_t gb = gB + col + c * 8;
        cpasync16(st + o,               g_khi + ga);
        cpasync16(st + G1_TILE + o,     g_klo + ga);
        cpasync16(st + 2 * G1_TILE + o, g_Whi + gb);
        cpasync16(st + 3 * G1_TILE + o, g_Wlo + gb);
    }
    CP_COMMIT();
}

__global__ __launch_bounds__(256, 2)
void gemm1_hmma(const float* __restrict__ v, float* __restrict__ out) {
    extern __shared__ char smem[];
    const uint32_t sbase = smem_u32(smem);
    const int tid = threadIdx.x;
    const int lane = tid & 31;
    const int wid = tid >> 5;
    const int n0 = blockIdx.x * 128;
    const int m0 = blockIdx.y * 128;

    // global->smem mapping: thread -> (row, 2 chunks of 16B)
    const int lrow = tid >> 1;
    const int lc = (tid & 1) * 2;
    const size_t gA = (size_t)(m0 + lrow) * KDIM;
    const size_t gB = (size_t)(n0 + lrow) * KDIM;

    float acc[4][4][4];
#pragma unroll
    for (int a = 0; a < 4; a++)
#pragma unroll
        for (int b = 0; b < 4; b++)
#pragma unroll
            for (int c = 0; c < 4; c++) acc[a][b][c] = 0.0f;

    g1_prefetch(sbase, 0, gA, gB, lrow, lc);
    g1_prefetch(sbase, 1, gA, gB, lrow, lc);

    const int wm = wid >> 2;      // 0..1
    const int wn = wid & 3;       // 0..3
    const int ri = lane & 7;
    const int q = lane >> 3;
    const int rowoff = (q & 1) * 8 + ri;   // row within 16-row tile
    const int cq = q >> 1;                 // k 16B-chunk select within k16

#pragma unroll 1
    for (int kc = 0; kc < G1_NCHUNK; kc++) {
        if (kc + 1 < G1_NCHUNK) { CP_WAIT(1); } else { CP_WAIT(0); }
        __syncthreads();
        if (kc + 2 < G1_NCHUNK) g1_prefetch(sbase, kc + 2, gA, gB, lrow, lc);

        const uint32_t bA = sbase + (uint32_t)(kc % 3) * G1_STAGE;
#pragma unroll
        for (int ks = 0; ks < 2; ks++) {
            const int c = ks * 2 + cq;
            uint32_t bh[2][4], bl[2][4];
#pragma unroll
            for (int nt = 0; nt < 2; nt++) {
                const int rB = wn * 32 + nt * 16 + rowoff;
                uint32_t addr = bA + 2 * G1_TILE + sw1(rB, c);
                ldmx4(addr, bh[nt]);
                ldmx4(addr + G1_TILE, bl[nt]);
            }
#pragma unroll
            for (int mi = 0; mi < 4; mi++) {
                const int rA = wm * 64 + mi * 16 + rowoff;
                uint32_t ah[4], al[4];
                uint32_t addr = bA + sw1(rA, c);
                ldmx4(addr, ah);
                ldmx4(addr + G1_TILE, al);
#pragma unroll
                for (int nj = 0; nj < 4; nj++) {
                    uint32_t b0h = bh[nj >> 1][nj & 1];
                    uint32_t b1h = bh[nj >> 1][2 + (nj & 1)];
                    uint32_t b0l = bl[nj >> 1][nj & 1];
                    uint32_t b1l = bl[nj >> 1][2 + (nj & 1)];
                    mma16816(acc[mi][nj], ah, b0h, b1h);   // hi*hi
                    mma16816(acc[mi][nj], al, b0h, b1h);   // lo*hi
                    mma16816(acc[mi][nj], ah, b0l, b1l);   // hi*lo
                }
            }
        }
    }

    // ---- epilogue: retrieved fp32, diff bf16, fused loss ----
    const int g = lane >> 2;
    const int t = lane & 3;
    float lp = 0.0f;
#pragma unroll
    for (int mi = 0; mi < 4; mi++) {
#pragma unroll
        for (int nj = 0; nj < 4; nj++) {
            int col = n0 + wn * 32 + nj * 8 + t * 2;
#pragma unroll
            for (int h = 0; h < 2; h++) {
                int row = m0 + wm * 64 + mi * 16 + g + h * 8;
                size_t off = (size_t)row * VDIM + col;
                float r0 = acc[mi][nj][2 * h];
                float r1 = acc[mi][nj][2 * h + 1];
                *(float2*)(out + off) = make_float2(r0, r1);
                float2 vv = *(const float2*)(v + off);
                float d0 = r0 - vv.x, d1 = r1 - vv.y;
                lp += d0 * d0 + d1 * d1;
                uint32_t db = ((uint32_t)__bfloat16_as_ushort(__float2bfloat16_rn(d1)) << 16)
                            | __bfloat16_as_ushort(__float2bfloat16_rn(d0));
                *(uint32_t*)(g_diff + off) = db;
            }
        }
    }

    __shared__ float red[256];
    red[tid] = lp;
    __syncthreads();
#pragma unroll
    for (int s = 128; s > 0; s >>= 1) {
        if (tid < s) red[tid] += red[tid + s];
        __syncthreads();
    }
    if (tid == 0) atomicAdd(&g_loss, red[0]);
}

// ---------------------------------------------------------------------------
// GEMM2 via HMMA: partial[s] = diff_split.T @ k_split (single-pass bf16).
// CTA 128(vd) x 128(kd), BK=64 batch rows, split-K over 16 splits.
// 3-stage pipeline, one barrier per chunk, XOR-swizzled 256B-pitch rows.
#define G2_TILE   16384                  // 64 rows x 256 B
#define G2_STAGE  (2 * G2_TILE)          // diff + k = 32768 B
#define G2_SMEM   (3 * G2_STAGE)         // 98304 B
#define G2_NCHUNK (ROWS_PER_SPLIT / 64)  // 64

// swizzled byte offset of 16B chunk `c` (0..15) in row `row` (256B pitch)
__device__ __forceinline__ uint32_t sw2(int row, int c) {
    return (uint32_t)(row * 256 + ((c ^ (row & 7)) << 4));
}

__device__ __forceinline__ void g2_prefetch(uint32_t sb, int bt, size_t b0,
                                            int vd0, int kd0, int lrow, int lc0) {
    const uint32_t st = sb + (uint32_t)(bt % 3) * G2_STAGE;
    const size_t gr = b0 + (size_t)bt * 64 + lrow;
#pragma unroll
    for (int u = 0; u < 4; u++) {
        const int c = lc0 + u;
        const uint32_t o = sw2(lrow, c);
        cpasync16(st + o,           g_diff + gr * VDIM + vd0 + c * 8);
        cpasync16(st + G2_TILE + o, g_khi + gr * KDIM + kd0 + c * 8);
    }
    CP_COMMIT();
}

__global__ __launch_bounds__(256, 2)
void gemm2_hmma() {
    extern __shared__ char smem[];
    const uint32_t sbase = smem_u32(smem);
    const int tid = threadIdx.x;
    const int lane = tid & 31;
    const int wid = tid >> 5;
    const int kd0 = blockIdx.x * 128;
    const int vd0 = blockIdx.y * 128;
    const int split = blockIdx.z;
    const size_t b0 = (size_t)split * ROWS_PER_SPLIT;

    // load mapping: thread -> (row of 64, 4 chunks of 16B)
    const int lrow = tid >> 2;
    const int lc0 = (tid & 3) * 4;

    float acc[4][4][4];
#pragma unroll
    for (int a = 0; a < 4; a++)
#pragma unroll
        for (int b = 0; b < 4; b++)
#pragma unroll
            for (int c = 0; c < 4; c++) acc[a][b][c] = 0.0f;

    g2_prefetch(sbase, 0, b0, vd0, kd0, lrow, lc0);
    g2_prefetch(sbase, 1, b0, vd0, kd0, lrow, lc0);

    const int wm = wid >> 2;
    const int wn = wid & 3;
    const int ri = lane & 7;
    const int q = lane >> 3;
    const int krowoff = (q >> 1) * 8 + ri;   // b-row within k16 block
    const int coloff = (q & 1) * 8;          // m/n column offset

#pragma unroll 1
    for (int bt = 0; bt < G2_NCHUNK; bt++) {
        if (bt + 1 < G2_NCHUNK) { CP_WAIT(1); } else { CP_WAIT(0); }
        __syncthreads();
        if (bt + 2 < G2_NCHUNK) g2_prefetch(sbase, bt + 2, b0, vd0, kd0, lrow, lc0);

        const uint32_t bA = sbase + (uint32_t)(bt % 3) * G2_STAGE;
#pragma unroll
        for (int ks = 0; ks < 4; ks++) {
            const int krow = ks * 16 + krowoff;
            uint32_t bf[2][4];
#pragma unroll
            for (int nt = 0; nt < 2; nt++) {
                const int col = wn * 32 + nt * 16 + coloff;
                ldmx4t(bA + G2_TILE + sw2(krow, col >> 3), bf[nt]);
            }
#pragma unroll
            for (int mi = 0; mi < 4; mi++) {
                const int col = wm * 64 + mi * 16 + coloff;
                uint32_t af[4];
                ldmx4t(bA + sw2(krow, col >> 3), af);
#pragma unroll
                for (int nj = 0; nj < 4; nj++) {
                    mma16816(acc[mi][nj], af,
                             bf[nj >> 1][nj & 1], bf[nj >> 1][2 + (nj & 1)]);
                }
            }
        }
    }

    // write split partials
    float* pb = g_partials[split];
    const int g = lane >> 2;
    const int t = lane & 3;
#pragma unroll
    for (int mi = 0; mi < 4; mi++) {
#pragma unroll
        for (int nj = 0; nj < 4; nj++) {
            int col = kd0 + wn * 32 + nj * 8 + t * 2;
#pragma unroll
            for (int h = 0; h < 2; h++) {
                int row = vd0 + wm * 64 + mi * 16 + g + h * 8;
                *(float2*)(pb + (size_t)row * KDIM + col) =
                    make_float2(acc[mi][nj][2 * h], acc[mi][nj][2 * h + 1]);
            }
        }
    }
}

// ---------------------------------------------------------------------------
__global__ void gates_kernel(const float* __restrict__ gate_w,
                             const float* __restrict__ gate_b) {
    int tid = threadIdx.x;
    int j = tid >> 5;
    int lane = tid & 31;
    float p = 0.0f;
    for (int i = lane; i < KDIM; i += 32) p += gate_w[j * KDIM + i] * g_colsum[i];
#pragma unroll
    for (int o = 16; o > 0; o >>= 1) p += __shfl_down_sync(0xffffffffu, p, o);
    if (lane == 0) {
        float x = p * (1.0f / (float)BROWS) + gate_b[j];
        g_gates[j] = 1.0f / (1.0f + expf(-x));
    }
}

// ---------------------------------------------------------------------------
__global__ void finalize_kernel(const float* __restrict__ W,
                                const float* __restrict__ S,
                                float* __restrict__ out) {
    int idx = blockIdx.x * blockDim.x + threadIdx.x;
    float alpha = g_gates[0];
    float eta = g_gates[1];
    float theta = g_gates[2];

    float g = 0.0f;
#pragma unroll
    for (int s = 0; s < NSPLIT; s++) g += g_partials[s][idx];
    g *= (2.0f / ((float)BROWS * (float)VDIM));

    float ns = eta * S[idx] - theta * g;
    float nw = (1.0f - alpha) * W[idx] + ns;

    const size_t RET = (size_t)BROWS * VDIM;
    out[RET + 1 + idx] = nw;
    out[RET + 1 + (size_t)VDIM * KDIM + idx] = ns;
    if (idx == 0) out[RET] = g_loss * (1.0f / ((float)BROWS * (float)VDIM));
}

// ---------------------------------------------------------------------------
extern "C" void kernel_launch(void* const* d_in, const int* in_sizes, int n_in,
                              void* d_out, int out_size) {
    const float* k  = (const float*)d_in[0];
    const float* v  = (const float*)d_in[1];
    const float* W  = (const float*)d_in[2];
    const float* S  = (const float*)d_in[3];
    const float* gw = (const float*)d_in[4];
    const float* gb = (const float*)d_in[5];
    float* out = (float*)d_out;

    cudaFuncSetAttribute(gemm1_hmma, cudaFuncAttributeMaxDynamicSharedMemorySize,
                         G1_SMEM);
    cudaFuncSetAttribute(gemm2_hmma, cudaFuncAttributeMaxDynamicSharedMemorySize,
                         G2_SMEM);

    __nv_bfloat16* whi; cudaGetSymbolAddress((void**)&whi, g_Whi);
    __nv_bfloat16* wlo; cudaGetSymbolAddress((void**)&wlo, g_Wlo);

    zero_kernel<<<1, 512>>>();
    convert_k_colsum<<<BROWS / 128, 256>>>(k);
    convert_split_kernel<<<(VDIM * KDIM) / 1024, 256>>>(W, whi, wlo);
    gemm1_hmma<<<dim3(4, BROWS / 128), 256, G1_SMEM>>>(v, out);
    gemm2_hmma<<<dim3(4, 4, NSPLIT), 256, G2_SMEM>>>();
    gates_kernel<<<1, 96>>>(gw, gb);
    finalize_kernel<<<(VDIM * KDIM) / 256, 256>>>(W, S, out);
}